// round 15
// baseline (speedup 1.0000x reference)
#include <cuda_runtime.h>
#include <math.h>
#include <stdint.h>

#define NN 8000
#define NS 4000
#define DD 64
#define HH 128
#define EK 15
#define KK 16
#define MAXDEG 256
#define NPAIR 120
#define OUTM (NS*NPAIR)
#define GC 16
#define NCELL (GC*GC*GC)

// ---------------- device scratch (static, no dynamic allocation) ----------------
__device__ __align__(16) float g_adj[NS*NS];          // 64 MB dense symmetric adjacency
__device__ unsigned long long g_key[NN];
__device__ int   g_cnt[NN];
__device__ __align__(16) float g_sx[NS*DD];
__device__ __align__(16) float g_sp[NS*4];            // x,y,z,sq
__device__ float g_G[NS*HH];
__device__ int   g_nbr[NS*EK];
__device__ int   g_deg[NS];
__device__ __align__(16) int   g_nzc[NS*MAXDEG];
__device__ __align__(16) float g_nzv[NS*MAXDEG];
__device__ float g_sqadj[NS];
__device__ int   g_knn[NS*KK];
// grid structures for exact kNN pruning
__device__ int   g_ccount[NCELL];
__device__ int   g_cellstart[NCELL+1];
__device__ int   g_ccur[NCELL];
__device__ int   g_cellof[NN];
__device__ __align__(16) float4 g_cp[NN];             // cell-sorted (pos, sq)
__device__ int   g_ci[NN];                            // cell-sorted selected-rank (>=NS if unselected)

__device__ __forceinline__ unsigned ord_f(float f){
    unsigned u = __float_as_uint(f);
    return (u & 0x80000000u) ? ~u : (u | 0x80000000u);   // ascending-float -> ascending-uint
}
__device__ __forceinline__ float iord_f(unsigned o){
    unsigned u = (o & 0x80000000u) ? (o & 0x7fffffffu) : ~o;
    return __uint_as_float(u);
}
__device__ __forceinline__ unsigned long long umin64(unsigned long long a, unsigned long long b){
    return a < b ? a : b;
}

// ---- XLA/Eigen fast tanh (f32), bit-exact replication ----
__device__ __forceinline__ float tanh_xla(float x){
    float ax = fabsf(x);
    if (ax < 0.0004f) return x;                           // XLA kCanUseApprox shortcut
    float xc = fminf(fmaxf(x, -7.90531110763549805f), 7.90531110763549805f);
    float x2 = __fmul_rn(xc, xc);
    float p = __fmaf_rn(x2, -2.76076847742355e-16f, 2.00018790482477e-13f);
    p = __fmaf_rn(x2, p, -8.60467152213735e-11f);
    p = __fmaf_rn(x2, p,  5.12229709037114e-08f);
    p = __fmaf_rn(x2, p,  1.48572235717979e-05f);
    p = __fmaf_rn(x2, p,  6.37261928875436e-04f);
    p = __fmaf_rn(x2, p,  4.89352455891786e-03f);
    p = __fmul_rn(p, xc);
    float q = __fmaf_rn(x2, 1.19825839466702e-06f, 1.18534705686654e-04f);
    q = __fmaf_rn(x2, q, 2.26843463243900e-03f);
    q = __fmaf_rn(x2, q, 4.89352518554385e-03f);
    return __fdiv_rn(p, q);
}
// XLA logistic expansion: 0.5 + 0.5 * tanh(0.5 * x)
__device__ __forceinline__ float sigmoid_xla(float v){
    return __fadd_rn(0.5f, __fmul_rn(0.5f, tanh_xla(__fmul_rn(0.5f, v))));
}
// XLA row-reduction warp tail: shfl_down butterfly 16..1, result in lane 0
__device__ __forceinline__ float warp_red_xla(float s){
    #pragma unroll
    for (int o = 16; o > 0; o >>= 1)
        s = __fadd_rn(s, __shfl_down_sync(0xffffffffu, s, o));
    return s;
}

// ---------------- G0: zero grid counters ----------------
__global__ void __launch_bounds__(256) k_grid_zero(){
    for (int i = threadIdx.x; i < NCELL; i += 256) g_ccount[i] = 0;
}

// ---------------- G1: bin all 8000 nodes ----------------
__global__ void __launch_bounds__(256) k_grid_bin(const float* __restrict__ pos){
    int n = blockIdx.x*256 + threadIdx.x;
    if (n >= NN) return;
    float px = pos[n*3], py = pos[n*3+1], pz = pos[n*3+2];
    int cx = min(GC-1, max(0, (int)(px*GC)));
    int cy = min(GC-1, max(0, (int)(py*GC)));
    int cz = min(GC-1, max(0, (int)(pz*GC)));
    int cell = (cz*GC + cy)*GC + cx;
    g_cellof[n] = cell;
    atomicAdd(&g_ccount[cell], 1);
}

// ---------------- G2: exclusive prefix sum over 4096 cells (single block) ----------------
__global__ void __launch_bounds__(256) k_grid_scan(){
    __shared__ int part[256];
    int tid = threadIdx.x;
    int base = tid*(NCELL/256);
    int s = 0;
    #pragma unroll
    for (int i = 0; i < NCELL/256; i++) s += g_ccount[base+i];
    part[tid] = s;
    __syncthreads();
    if (tid == 0){
        int acc = 0;
        for (int i = 0; i < 256; i++){ int t = part[i]; part[i] = acc; acc += t; }
    }
    __syncthreads();
    int acc = part[tid];
    #pragma unroll
    for (int i = 0; i < NCELL/256; i++){
        int t = g_ccount[base+i];
        g_cellstart[base+i] = acc;
        g_ccur[base+i] = acc;
        acc += t;
    }
    if (tid == 255) g_cellstart[NCELL] = NN;
}

// ---------------- G3: scatter nodes into cell order (after rank_a: embeds rank) ----------------
// sq computed with the SAME op sequence as sel_gather -> bit-identical to g_sp[..].w
__global__ void __launch_bounds__(256) k_grid_scatter(const float* __restrict__ pos){
    int n = blockIdx.x*256 + threadIdx.x;
    if (n >= NN) return;
    float px = pos[n*3], py = pos[n*3+1], pz = pos[n*3+2];
    float sq = __fadd_rn(__fadd_rn(__fmul_rn(px,px), __fmul_rn(py,py)), __fmul_rn(pz,pz));
    int off = atomicAdd(&g_ccur[g_cellof[n]], 1);       // within-cell order nondet: OK,
    g_cp[off] = make_float4(px, py, pz, sq);            // selection below is key-min (order-free)
    g_ci[off] = g_cnt[n];                               // rank; >=NS if unselected
}

// ---------------- K1: probs = sigmoid_xla(relu(x@W1+b1)@w2), warp per node ----------------
// Also zeroes g_cnt (rank counters) — runs before k_rank_a in stream order.
__global__ void __launch_bounds__(128) k_probs(const float* __restrict__ x,
                        const float* __restrict__ W1,
                        const float* __restrict__ b1, const float* __restrict__ w2){
    __shared__ float xs[4][DD];
    __shared__ float sW1[DD*HH];                // 32 KB
    int warp = threadIdx.x >> 5, lane = threadIdx.x & 31;
    const float4* wsrc = reinterpret_cast<const float4*>(W1);
    float4* wdst = reinterpret_cast<float4*>(sW1);
    #pragma unroll
    for (int u = 0; u < (DD*HH/4)/128; u++)
        wdst[threadIdx.x + 128*u] = wsrc[threadIdx.x + 128*u];
    int n = blockIdx.x*4 + warp;                // 8000 nodes, 4 warps/block, grid=2000
    if (lane == 0) g_cnt[n] = 0;                // reset rank counter for this replay
    xs[warp][lane]      = x[n*DD + lane];
    xs[warp][lane + 32] = x[n*DD + lane + 32];
    __syncthreads();
    float s = 0.f;
    #pragma unroll
    for (int j = 0; j < 4; j++){
        int k = lane + 32*j;
        float h = 0.f;
        #pragma unroll
        for (int d = 0; d < DD; d++) h = __fmaf_rn(xs[warp][d], sW1[d*HH + k], h);
        h = fmaxf(__fadd_rn(h, b1[k]), 0.f);
        float m = __fmul_rn(h, w2[k]);
        s = __fadd_rn(s, m);                    // sequential ascending-j adds
    }
    s = warp_red_xla(s);
    if (lane == 0){
        float p = sigmoid_xla(s);
        g_key[n] = ((unsigned long long)ord_f(p) << 32) | (unsigned)(NN - 1 - n); // tie->lower n
    }
}

// ---------------- K2a: partial exact ranking (quarter scans, int-atomic merge) ----------------
__global__ void __launch_bounds__(256) k_rank_a(){
    __shared__ unsigned long long sk[256];
    int qt = blockIdx.x >> 5;                   // quarter 0..3
    int nb = blockIdx.x & 31;                   // node block 0..31
    int n = nb*256 + threadIdx.x;               // 0..8191
    unsigned long long my = (n < NN) ? g_key[n] : 0ULL;
    int cnt = 0;
    int lo = qt*(NN/4), hi = lo + NN/4;         // 2000-wide key range
    for (int base = lo; base < hi; base += 256){
        int idx = base + threadIdx.x;
        sk[threadIdx.x] = (idx < hi) ? g_key[idx] : 0ULL;
        __syncthreads();
        int lim = min(256, hi - base);
        for (int k = 0; k < lim; k++) cnt += (sk[k] > my) ? 1 : 0;
        __syncthreads();
    }
    if (n < NN && cnt > 0) atomicAdd(&g_cnt[n], cnt);   // int add: order-independent exact
}

// ---------------- K2b+K3 fused: each selected node writes its own row ----------------
__global__ void __launch_bounds__(256) k_sel_gather(const float* __restrict__ x,
                         const float* __restrict__ pos,
                         const float* __restrict__ Wf1){
    __shared__ float xs[8][DD];
    int warp = threadIdx.x >> 5, lane = threadIdx.x & 31;
    int n = blockIdx.x*8 + warp;                // 1000 blocks x 8 warps = 8000 nodes
    int c = g_cnt[n];
    if (c >= NS) return;                        // not selected: whole warp exits
    int r = c;
    float x0 = x[n*DD + lane], x1 = x[n*DD + lane + 32];
    xs[warp][lane] = x0; xs[warp][lane + 32] = x1;
    g_sx[r*DD + lane] = x0; g_sx[r*DD + lane + 32] = x1;
    float pv = (lane < 3) ? pos[n*3 + lane] : 0.f;
    if (lane < 3) g_sp[r*4 + lane] = pv;
    float ppx = __shfl_sync(0xffffffffu, pv, 0);
    float ppy = __shfl_sync(0xffffffffu, pv, 1);
    float ppz = __shfl_sync(0xffffffffu, pv, 2);
    if (lane == 0){
        // sq = (x^2 + y^2) + z^2, squares rounded separately (square-then-reduce, NO fma)
        float sq = __fadd_rn(__fadd_rn(__fmul_rn(ppx,ppx), __fmul_rn(ppy,ppy)),
                             __fmul_rn(ppz,ppz));
        g_sp[r*4 + 3] = sq;
    }
    __syncwarp();
    float g0 = 0.f, g1 = 0.f, g2 = 0.f, g3 = 0.f;
    int t0 = lane, t1 = lane + 32, t2 = lane + 64, t3 = lane + 96;
    #pragma unroll
    for (int d = 0; d < DD; d++){
        float v = xs[warp][d];
        const float* wrow = &Wf1[d*HH];
        g0 = fmaf(v, wrow[t0], g0);
        g1 = fmaf(v, wrow[t1], g1);
        g2 = fmaf(v, wrow[t2], g2);
        g3 = fmaf(v, wrow[t3], g3);
    }
    {
        const float* wrow = &Wf1[DD*HH];
        g0 = fmaf(ppx, wrow[t0], g0); g1 = fmaf(ppx, wrow[t1], g1);
        g2 = fmaf(ppx, wrow[t2], g2); g3 = fmaf(ppx, wrow[t3], g3);
        wrow += HH;
        g0 = fmaf(ppy, wrow[t0], g0); g1 = fmaf(ppy, wrow[t1], g1);
        g2 = fmaf(ppy, wrow[t2], g2); g3 = fmaf(ppy, wrow[t3], g3);
        wrow += HH;
        g0 = fmaf(ppz, wrow[t0], g0); g1 = fmaf(ppz, wrow[t1], g1);
        g2 = fmaf(ppz, wrow[t2], g2); g3 = fmaf(ppz, wrow[t3], g3);
    }
    g_G[r*HH + t0] = g0; g_G[r*HH + t1] = g1;
    g_G[r*HH + t2] = g2; g_G[r*HH + t3] = g3;
}

// ---------------- K4: exact 15-NN via grid ring search (thread per row) ----------------
// Top-15 kept as u64 keys (ord(d2), sel_idx): order-independent == lax.top_k (unique keys,
// ties -> lower selected idx). Stop rule: after completing Chebyshev ring R, unvisited
// points have true d2 >= (R*h)^2; computed d2 >= that - ~3e-7, so if k14_d2 < (R*h)^2-1e-6
// nothing unvisited can displace. Else expand; cap = full grid (unconditionally exact).
__global__ void __launch_bounds__(32) k_knn_pos(){
    int r = blockIdx.x*32 + threadIdx.x;          // 125 blocks x 32
    float4 m = *reinterpret_cast<const float4*>(&g_sp[r*4]);
    float px = m.x, py = m.y, pz = m.z, sqi = m.w;
    int cx = min(GC-1, max(0, (int)(px*GC)));
    int cy = min(GC-1, max(0, (int)(py*GC)));
    int cz = min(GC-1, max(0, (int)(pz*GC)));
    const float h = 1.0f/GC;
    unsigned long long k[EK];
    #pragma unroll
    for (int s = 0; s < EK; s++) k[s] = ~0ULL;
    for (int R = 0; R < GC; R++){
        int zlo = max(cz-R, 0), zhi = min(cz+R, GC-1);
        int ylo = max(cy-R, 0), yhi = min(cy+R, GC-1);
        int xlo = max(cx-R, 0), xhi = min(cx+R, GC-1);
        for (int z = zlo; z <= zhi; z++){
            int az = abs(z-cz);
            for (int y = ylo; y <= yhi; y++){
                int ay = max(az, abs(y-cy));
                for (int x = xlo; x <= xhi; x++){
                    int ch = max(ay, abs(x-cx));
                    if (ch != R) continue;        // shell only
                    int cell = (z*GC + y)*GC + x;
                    int e1 = g_cellstart[cell+1];
                    for (int e = g_cellstart[cell]; e < e1; e++){
                        int sc = g_ci[e];
                        if (sc >= NS || sc == r) continue;
                        float4 q = g_cp[e];
                        // acc=0; fma k=0,1,2 -> fma(z,qz, fma(y,qy, round(x*qx)))  [pass bits]
                        float dot = __fmaf_rn(pz, q.z, __fmaf_rn(py, q.y, __fmul_rn(px, q.x)));
                        float d2  = __fsub_rn(__fadd_rn(sqi, q.w), __fmul_rn(2.f, dot));
                        unsigned long long key =
                            ((unsigned long long)ord_f(d2) << 32) | (unsigned)sc;
                        if (key < k[EK-1]){
                            int pos = 0;
                            #pragma unroll
                            for (int s = 0; s < EK; s++) pos += (k[s] <= key) ? 1 : 0;
                            #pragma unroll
                            for (int s = EK-1; s > 0; s--) if (s > pos) k[s] = k[s-1];
                            #pragma unroll
                            for (int s = 0; s < EK; s++) if (s == pos) k[s] = key;
                        }
                    }
                }
            }
        }
        if (R >= 1){
            float d15 = iord_f((unsigned)(k[EK-1] >> 32));   // NaN while list not full -> no break
            float b = R*h;
            if (d15 < __fmaf_rn(b, b, -1e-6f)) break;
        }
    }
    #pragma unroll
    for (int s = 0; s < EK; s++) g_nbr[r*EK + s] = (int)(k[s] & 0xFFFFFFFFu);
}

// ---------------- K0: zero adjacency (after knn, before edges) ----------------
__global__ void __launch_bounds__(256) k_zero_adj(){
    float4 z = make_float4(0.f,0.f,0.f,0.f);
    float4* p = reinterpret_cast<float4*>(g_adj);
    const int n4 = (NS*NS)/4;
    for (int i = blockIdx.x*blockDim.x + threadIdx.x; i < n4; i += gridDim.x*blockDim.x)
        p[i] = z;
}

// ---------------- K5: edge probs, warp per edge (XLA mult+row-reduce shape) ----------------
__global__ void __launch_bounds__(256) k_edges(const float* __restrict__ we){
    int e = blockIdx.x*8 + (threadIdx.x >> 5);
    int lane = threadIdx.x & 31;
    if (e >= NS*EK) return;
    int i = e / EK;
    int j = g_nbr[e];
    const float* a = &g_sx[i*DD];
    const float* b = &g_sx[j*DD];
    // z_k = round(a_k*b_k); m_k = round(z_k*w_k); lane partial = m_lane + m_{lane+32}
    float m0 = __fmul_rn(__fmul_rn(a[lane],      b[lane]),      we[lane]);
    float m1 = __fmul_rn(__fmul_rn(a[lane + 32], b[lane + 32]), we[lane + 32]);
    float s  = __fadd_rn(m0, m1);
    s = warp_red_xla(s);
    if (lane == 0){
        float ep = sigmoid_xla(s);
        g_adj[i*NS + j] = ep;    // symmetric/duplicate writes identical bits: race-free
        g_adj[j*NS + i] = ep;
    }
}

// ---------------- K6: per-row sparse nz lists (column-ascending, deterministic) ----------------
__global__ void __launch_bounds__(256) k_nzlist(){
    int wid  = (blockIdx.x*blockDim.x + threadIdx.x) >> 5;
    int lane = threadIdx.x & 31;
    if (wid >= NS) return;
    int cnt = 0;
    for (int base = 0; base < NS; base += 32){
        float v = g_adj[wid*NS + base + lane];
        unsigned m = __ballot_sync(0xffffffffu, v != 0.f);
        if (v != 0.f){
            int pos = cnt + __popc(m & ((1u << lane) - 1u));
            if (pos < MAXDEG){ g_nzc[wid*MAXDEG + pos] = base + lane; g_nzv[wid*MAXDEG + pos] = v; }
        }
        cnt += __popc(m);
    }
    int deg = min(cnt, MAXDEG);
    if (lane == 0){
        g_deg[wid] = deg;
        // ||row||^2: ascending-column sequential (zeros contribute exact 0 in any order)
        float s = 0.f;
        for (int t = 0; t < deg; t++){
            float v = g_nzv[wid*MAXDEG + t];
            s = __fadd_rn(s, __fmul_rn(v, v));
        }
        g_sqadj[wid] = s;
    }
}

// ---------------- K7: sparse adj@adjT row, fd2, exact 16-NN (prefetch pipeline) ----------------
__global__ void __launch_bounds__(256) k_fd2knn(){
    __shared__ float sfd[NS];                    // 16 KB accumulate buffer
    __shared__ int   sic[MAXDEG];
    __shared__ float siv[MAXDEG];
    __shared__ int   sdeg[MAXDEG];
    __shared__ unsigned long long swin[8];
    __shared__ unsigned long long sbest;
    int i = blockIdx.x, t = threadIdx.x;         // 256 threads
    int lane = t & 31, warp = t >> 5;
    for (int k = t; k < NS; k += 256) sfd[k] = 0.f;
    int degi = g_deg[i];
    if (t < degi){ sic[t] = g_nzc[i*MAXDEG + t]; siv[t] = g_nzv[i*MAXDEG + t]; }
    __syncthreads();
    if (t < degi) sdeg[t] = g_deg[sic[t]];       // all neighbor degrees up front
    __syncthreads();
    // depth-2 software prefetch: (col,val) for iterations jj and jj+1 live in registers
    int   c0 = -1, c1 = -1;
    float v0 = 0.f, v1 = 0.f;
    if (0 < degi && t < sdeg[0]){ c0 = g_nzc[sic[0]*MAXDEG + t]; v0 = g_nzv[sic[0]*MAXDEG + t]; }
    if (1 < degi && t < sdeg[1]){ c1 = g_nzc[sic[1]*MAXDEG + t]; v1 = g_nzv[sic[1]*MAXDEG + t]; }
    for (int jj = 0; jj < degi; jj++){           // ascending-j == dense ascending-k bitwise
        int   c2 = -1; float v2 = 0.f;
        if (jj + 2 < degi && t < sdeg[jj+2]){    // issue next loads before the barrier
            c2 = g_nzc[sic[jj+2]*MAXDEG + t];
            v2 = g_nzv[sic[jj+2]*MAXDEG + t];
        }
        float aij = siv[jj];
        if (c0 >= 0) sfd[c0] = __fmaf_rn(aij, v0, sfd[c0]);  // distinct k within one j
        __syncthreads();
        c0 = c1; v0 = v1; c1 = c2; v1 = v2;
    }
    float sqi = g_sqadj[i];
    unsigned long long lk[16];
    #pragma unroll
    for (int m = 0; m < 16; m++){
        int k = t + 256*m;
        unsigned long long key = ~0ULL;
        if (k < NS && k != i){
            float fd = __fsub_rn(__fadd_rn(sqi, g_sqadj[k]), __fmul_rn(2.f, sfd[k]));
            key = ((unsigned long long)ord_f(fd) << 32) | (unsigned)k;
        }
        lk[m] = key;
    }
    unsigned long long lmin = lk[0];
    #pragma unroll
    for (int m = 1; m < 16; m++) lmin = umin64(lmin, lk[m]);
    for (int r = 0; r < KK; r++){
        unsigned long long b = lmin;
        #pragma unroll
        for (int o = 16; o > 0; o >>= 1) b = umin64(b, __shfl_down_sync(0xffffffffu, b, o));
        if (lane == 0) swin[warp] = b;
        __syncthreads();
        if (t == 0){
            unsigned long long bb = swin[0];
            #pragma unroll
            for (int w = 1; w < 8; w++) bb = umin64(bb, swin[w]);
            sbest = bb;
            g_knn[i*KK + r] = (int)(bb & 0xFFFFFFFFu);
        }
        __syncthreads();
        unsigned long long best = sbest;
        if (lmin == best){                       // unique key (idx embedded): one owner
            #pragma unroll
            for (int m = 0; m < 16; m++) if (lk[m] == best) lk[m] = ~0ULL;
            lmin = lk[0];
            #pragma unroll
            for (int m = 1; m < 16; m++) lmin = umin64(lmin, lk[m]);
        }
        __syncthreads();
    }
}

// ---------------- K8: triangles, warp per pair (XLA matvec reduce for hf@wf2) ----------------
__global__ void __launch_bounds__(256) k_tri(const float* __restrict__ bf1,
                      const float* __restrict__ wf2,
                      float* __restrict__ out){
    __shared__ int   sk[KK];
    __shared__ float sAi[KK];
    __shared__ float sGi[HH];
    __shared__ float sGn[KK][HH+4];              // padded to dodge bank conflicts
    __shared__ float sb[HH], sw[HH];
    int i = blockIdx.x, t = threadIdx.x;         // 256 threads, 8 warps
    int lane = t & 31, warp = t >> 5;
    if (t < KK) sk[t] = g_knn[i*KK + t];
    if (t < HH){ sGi[t] = g_G[i*HH + t]; sb[t] = bf1[t]; sw[t] = wf2[t]; }
    __syncthreads();
    if (t < KK) sAi[t] = g_adj[i*NS + sk[t]];
    for (int q = warp; q < KK; q += 8){
        sGn[q][lane]      = g_G[sk[q]*HH + lane];
        sGn[q][lane+32]   = g_G[sk[q]*HH + lane + 32];
        sGn[q][lane+64]   = g_G[sk[q]*HH + lane + 64];
        sGn[q][lane+96]   = g_G[sk[q]*HH + lane + 96];
    }
    __syncthreads();
    const float third = 1.0f/3.0f;
    #pragma unroll
    for (int it = 0; it < NPAIR/8; it++){        // 15 iterations x 8 warps = 120 pairs
        int p0 = it*8 + warp;
        int p = p0, j = 0;
        while (p >= (KK - 1 - j)){ p -= (KK - 1 - j); j++; }   // triu_indices(16,1) order
        int l = j + 1 + p;
        // hf@wf2: lane partials k=lane+32m (rounded products, sequential adds), butterfly
        float s = 0.f;
        #pragma unroll
        for (int m = 0; m < 4; m++){
            int k = lane + 32*m;
            float pre = (sGi[k] + sGn[j][k] + sGn[l][k]) * third + sb[k];  // value-only path
            float hf  = fmaxf(pre, 0.f);
            s = __fadd_rn(s, __fmul_rn(hf, sw[k]));
        }
        s = warp_red_xla(s);
        if (lane == 0){
            int n1 = sk[j], n2 = sk[l];
            float a12  = g_adj[n1*NS + n2];
            bool valid = a12 > 0.f;
            float prod = __fmul_rn(__fmul_rn(sAi[j], sAi[l]), a12);
            float tpr  = valid ? cbrtf(fmaxf(prod, 1e-9f)) : 0.f;
            float fpr  = valid ? sigmoid_xla(s) : 0.f;
            out[i*NPAIR + p0]        = fpr;
            out[OUTM + i*NPAIR + p0] = tpr;
        }
    }
}

// ---------------- launch ----------------
extern "C" void kernel_launch(void* const* d_in, const int* in_sizes, int n_in,
                              void* d_out, int out_size){
    (void)in_sizes; (void)n_in; (void)out_size;
    const float* x   = (const float*)d_in[0];
    const float* pos = (const float*)d_in[1];
    const float* W1  = (const float*)d_in[2];
    const float* b1  = (const float*)d_in[3];
    const float* w2  = (const float*)d_in[4];
    const float* we  = (const float*)d_in[5];
    const float* Wf1 = (const float*)d_in[6];
    const float* bf1 = (const float*)d_in[7];
    const float* wf2 = (const float*)d_in[8];
    float* out = (float*)d_out;

    k_grid_zero<<<1, 256>>>();                   // idx 0
    k_grid_bin<<<(NN+255)/256, 256>>>(pos);      // idx 1
    k_grid_scan<<<1, 256>>>();                   // idx 2
    k_probs<<<NN/4, 128>>>(x, W1, b1, w2);       // idx 3  <- ncu capture target
    k_rank_a<<<128, 256>>>();                    // idx 4
    k_grid_scatter<<<(NN+255)/256, 256>>>(pos);  // idx 5 (needs g_cnt)
    k_sel_gather<<<NN/8, 256>>>(x, pos, Wf1);    // idx 6
    k_knn_pos<<<125, 32>>>();                    // idx 7 (grid-pruned exact 15-NN)
    k_zero_adj<<<1184, 256>>>();                 // idx 8
    k_edges<<<(NS*EK + 7)/8, 256>>>(we);         // idx 9
    k_nzlist<<<NS/8, 256>>>();                   // idx 10
    k_fd2knn<<<NS, 256>>>();                     // idx 11
    k_tri<<<NS, 256>>>(bf1, wf2, out);           // idx 12
}

// round 16
// speedup vs baseline: 1.6143x; 1.6143x over previous
#include <cuda_runtime.h>
#include <math.h>
#include <stdint.h>

#define NN 8000
#define NS 4000
#define DD 64
#define HH 128
#define EK 15
#define KK 16
#define MAXDEG 256
#define NPAIR 120
#define OUTM (NS*NPAIR)
#define GC 16
#define NCELL (GC*GC*GC)

// ---------------- device scratch (static, no dynamic allocation) ----------------
__device__ __align__(16) float g_adj[NS*NS];          // 64 MB dense symmetric adjacency
__device__ unsigned long long g_key[NN];
__device__ int   g_cnt[NN];
__device__ __align__(16) float g_sx[NS*DD];
__device__ __align__(16) float g_sp[NS*4];            // x,y,z,sq
__device__ float g_G[NS*HH];
__device__ int   g_nbr[NS*EK];
__device__ int   g_deg[NS];
__device__ __align__(16) int   g_nzc[NS*MAXDEG];
__device__ __align__(16) float g_nzv[NS*MAXDEG];
__device__ float g_sqadj[NS];
__device__ int   g_knn[NS*KK];
// grid structures for exact kNN pruning
__device__ int   g_ccount[NCELL];
__device__ int   g_cellstart[NCELL+1];
__device__ int   g_ccur[NCELL];
__device__ int   g_cellof[NN];
__device__ __align__(16) float4 g_cp[NN];             // cell-sorted (pos, sq)
__device__ int   g_ci[NN];                            // cell-sorted selected-rank (>=NS if unselected)

__device__ __forceinline__ unsigned ord_f(float f){
    unsigned u = __float_as_uint(f);
    return (u & 0x80000000u) ? ~u : (u | 0x80000000u);   // ascending-float -> ascending-uint
}
__device__ __forceinline__ float iord_f(unsigned o){
    unsigned u = (o & 0x80000000u) ? (o & 0x7fffffffu) : ~o;
    return __uint_as_float(u);
}
__device__ __forceinline__ unsigned long long umin64(unsigned long long a, unsigned long long b){
    return a < b ? a : b;
}

// ---- XLA/Eigen fast tanh (f32), bit-exact replication ----
__device__ __forceinline__ float tanh_xla(float x){
    float ax = fabsf(x);
    if (ax < 0.0004f) return x;                           // XLA kCanUseApprox shortcut
    float xc = fminf(fmaxf(x, -7.90531110763549805f), 7.90531110763549805f);
    float x2 = __fmul_rn(xc, xc);
    float p = __fmaf_rn(x2, -2.76076847742355e-16f, 2.00018790482477e-13f);
    p = __fmaf_rn(x2, p, -8.60467152213735e-11f);
    p = __fmaf_rn(x2, p,  5.12229709037114e-08f);
    p = __fmaf_rn(x2, p,  1.48572235717979e-05f);
    p = __fmaf_rn(x2, p,  6.37261928875436e-04f);
    p = __fmaf_rn(x2, p,  4.89352455891786e-03f);
    p = __fmul_rn(p, xc);
    float q = __fmaf_rn(x2, 1.19825839466702e-06f, 1.18534705686654e-04f);
    q = __fmaf_rn(x2, q, 2.26843463243900e-03f);
    q = __fmaf_rn(x2, q, 4.89352518554385e-03f);
    return __fdiv_rn(p, q);
}
// XLA logistic expansion: 0.5 + 0.5 * tanh(0.5 * x)
__device__ __forceinline__ float sigmoid_xla(float v){
    return __fadd_rn(0.5f, __fmul_rn(0.5f, tanh_xla(__fmul_rn(0.5f, v))));
}
// XLA row-reduction warp tail: shfl_down butterfly 16..1, result in lane 0
__device__ __forceinline__ float warp_red_xla(float s){
    #pragma unroll
    for (int o = 16; o > 0; o >>= 1)
        s = __fadd_rn(s, __shfl_down_sync(0xffffffffu, s, o));
    return s;
}

// ---------------- G0: zero grid counters ----------------
__global__ void __launch_bounds__(256) k_grid_zero(){
    for (int i = threadIdx.x; i < NCELL; i += 256) g_ccount[i] = 0;
}

// ---------------- G1: bin all 8000 nodes ----------------
__global__ void __launch_bounds__(256) k_grid_bin(const float* __restrict__ pos){
    int n = blockIdx.x*256 + threadIdx.x;
    if (n >= NN) return;
    float px = pos[n*3], py = pos[n*3+1], pz = pos[n*3+2];
    int cx = min(GC-1, max(0, (int)(px*GC)));
    int cy = min(GC-1, max(0, (int)(py*GC)));
    int cz = min(GC-1, max(0, (int)(pz*GC)));
    int cell = (cz*GC + cy)*GC + cx;
    g_cellof[n] = cell;
    atomicAdd(&g_ccount[cell], 1);
}

// ---------------- G2: exclusive prefix sum over 4096 cells (single block) ----------------
__global__ void __launch_bounds__(256) k_grid_scan(){
    __shared__ int part[256];
    int tid = threadIdx.x;
    int base = tid*(NCELL/256);
    int s = 0;
    #pragma unroll
    for (int i = 0; i < NCELL/256; i++) s += g_ccount[base+i];
    part[tid] = s;
    __syncthreads();
    if (tid == 0){
        int acc = 0;
        for (int i = 0; i < 256; i++){ int t = part[i]; part[i] = acc; acc += t; }
    }
    __syncthreads();
    int acc = part[tid];
    #pragma unroll
    for (int i = 0; i < NCELL/256; i++){
        int t = g_ccount[base+i];
        g_cellstart[base+i] = acc;
        g_ccur[base+i] = acc;
        acc += t;
    }
    if (tid == 255) g_cellstart[NCELL] = NN;
}

// ---------------- G3: scatter nodes into cell order (after rank_a: embeds rank) ----------------
// sq computed with the SAME op sequence as sel_gather -> bit-identical to g_sp[..].w
__global__ void __launch_bounds__(256) k_grid_scatter(const float* __restrict__ pos){
    int n = blockIdx.x*256 + threadIdx.x;
    if (n >= NN) return;
    float px = pos[n*3], py = pos[n*3+1], pz = pos[n*3+2];
    float sq = __fadd_rn(__fadd_rn(__fmul_rn(px,px), __fmul_rn(py,py)), __fmul_rn(pz,pz));
    int off = atomicAdd(&g_ccur[g_cellof[n]], 1);       // within-cell order nondet: OK,
    g_cp[off] = make_float4(px, py, pz, sq);            // selection below is key-min (order-free)
    g_ci[off] = g_cnt[n];                               // rank; >=NS if unselected
}

// ---------------- K1: probs = sigmoid_xla(relu(x@W1+b1)@w2), warp per node ----------------
// Also zeroes g_cnt (rank counters) — runs before k_rank_a in stream order.
__global__ void __launch_bounds__(128) k_probs(const float* __restrict__ x,
                        const float* __restrict__ W1,
                        const float* __restrict__ b1, const float* __restrict__ w2){
    __shared__ float xs[4][DD];
    __shared__ float sW1[DD*HH];                // 32 KB
    int warp = threadIdx.x >> 5, lane = threadIdx.x & 31;
    const float4* wsrc = reinterpret_cast<const float4*>(W1);
    float4* wdst = reinterpret_cast<float4*>(sW1);
    #pragma unroll
    for (int u = 0; u < (DD*HH/4)/128; u++)
        wdst[threadIdx.x + 128*u] = wsrc[threadIdx.x + 128*u];
    int n = blockIdx.x*4 + warp;                // 8000 nodes, 4 warps/block, grid=2000
    if (lane == 0) g_cnt[n] = 0;                // reset rank counter for this replay
    xs[warp][lane]      = x[n*DD + lane];
    xs[warp][lane + 32] = x[n*DD + lane + 32];
    __syncthreads();
    float s = 0.f;
    #pragma unroll
    for (int j = 0; j < 4; j++){
        int k = lane + 32*j;
        float h = 0.f;
        #pragma unroll
        for (int d = 0; d < DD; d++) h = __fmaf_rn(xs[warp][d], sW1[d*HH + k], h);
        h = fmaxf(__fadd_rn(h, b1[k]), 0.f);
        float m = __fmul_rn(h, w2[k]);
        s = __fadd_rn(s, m);                    // sequential ascending-j adds
    }
    s = warp_red_xla(s);
    if (lane == 0){
        float p = sigmoid_xla(s);
        g_key[n] = ((unsigned long long)ord_f(p) << 32) | (unsigned)(NN - 1 - n); // tie->lower n
    }
}

// ---------------- K2a: partial exact ranking (quarter scans, int-atomic merge) ----------------
__global__ void __launch_bounds__(256) k_rank_a(){
    __shared__ unsigned long long sk[256];
    int qt = blockIdx.x >> 5;                   // quarter 0..3
    int nb = blockIdx.x & 31;                   // node block 0..31
    int n = nb*256 + threadIdx.x;               // 0..8191
    unsigned long long my = (n < NN) ? g_key[n] : 0ULL;
    int cnt = 0;
    int lo = qt*(NN/4), hi = lo + NN/4;         // 2000-wide key range
    for (int base = lo; base < hi; base += 256){
        int idx = base + threadIdx.x;
        sk[threadIdx.x] = (idx < hi) ? g_key[idx] : 0ULL;
        __syncthreads();
        int lim = min(256, hi - base);
        for (int k = 0; k < lim; k++) cnt += (sk[k] > my) ? 1 : 0;
        __syncthreads();
    }
    if (n < NN && cnt > 0) atomicAdd(&g_cnt[n], cnt);   // int add: order-independent exact
}

// ---------------- K2b+K3 fused: each selected node writes its own row ----------------
__global__ void __launch_bounds__(256) k_sel_gather(const float* __restrict__ x,
                         const float* __restrict__ pos,
                         const float* __restrict__ Wf1){
    __shared__ float xs[8][DD];
    int warp = threadIdx.x >> 5, lane = threadIdx.x & 31;
    int n = blockIdx.x*8 + warp;                // 1000 blocks x 8 warps = 8000 nodes
    int c = g_cnt[n];
    if (c >= NS) return;                        // not selected: whole warp exits
    int r = c;
    float x0 = x[n*DD + lane], x1 = x[n*DD + lane + 32];
    xs[warp][lane] = x0; xs[warp][lane + 32] = x1;
    g_sx[r*DD + lane] = x0; g_sx[r*DD + lane + 32] = x1;
    float pv = (lane < 3) ? pos[n*3 + lane] : 0.f;
    if (lane < 3) g_sp[r*4 + lane] = pv;
    float ppx = __shfl_sync(0xffffffffu, pv, 0);
    float ppy = __shfl_sync(0xffffffffu, pv, 1);
    float ppz = __shfl_sync(0xffffffffu, pv, 2);
    if (lane == 0){
        // sq = (x^2 + y^2) + z^2, squares rounded separately (square-then-reduce, NO fma)
        float sq = __fadd_rn(__fadd_rn(__fmul_rn(ppx,ppx), __fmul_rn(ppy,ppy)),
                             __fmul_rn(ppz,ppz));
        g_sp[r*4 + 3] = sq;
    }
    __syncwarp();
    float g0 = 0.f, g1 = 0.f, g2 = 0.f, g3 = 0.f;
    int t0 = lane, t1 = lane + 32, t2 = lane + 64, t3 = lane + 96;
    #pragma unroll
    for (int d = 0; d < DD; d++){
        float v = xs[warp][d];
        const float* wrow = &Wf1[d*HH];
        g0 = fmaf(v, wrow[t0], g0);
        g1 = fmaf(v, wrow[t1], g1);
        g2 = fmaf(v, wrow[t2], g2);
        g3 = fmaf(v, wrow[t3], g3);
    }
    {
        const float* wrow = &Wf1[DD*HH];
        g0 = fmaf(ppx, wrow[t0], g0); g1 = fmaf(ppx, wrow[t1], g1);
        g2 = fmaf(ppx, wrow[t2], g2); g3 = fmaf(ppx, wrow[t3], g3);
        wrow += HH;
        g0 = fmaf(ppy, wrow[t0], g0); g1 = fmaf(ppy, wrow[t1], g1);
        g2 = fmaf(ppy, wrow[t2], g2); g3 = fmaf(ppy, wrow[t3], g3);
        wrow += HH;
        g0 = fmaf(ppz, wrow[t0], g0); g1 = fmaf(ppz, wrow[t1], g1);
        g2 = fmaf(ppz, wrow[t2], g2); g3 = fmaf(ppz, wrow[t3], g3);
    }
    g_G[r*HH + t0] = g0; g_G[r*HH + t1] = g1;
    g_G[r*HH + t2] = g2; g_G[r*HH + t3] = g3;
}

// ---- guarded exact insertion into a sorted 15-key register list ----
#define INSKEY(KARR, KEY) do{ \
    if ((KEY) < KARR[EK-1]){ \
        int pos = 0; \
        _Pragma("unroll") \
        for (int s = 0; s < EK; s++) pos += (KARR[s] <= (KEY)) ? 1 : 0; \
        _Pragma("unroll") \
        for (int s = EK-1; s > 0; s--) if (s > pos) KARR[s] = KARR[s-1]; \
        _Pragma("unroll") \
        for (int s = 0; s < EK; s++) if (s == pos) KARR[s] = (KEY); \
    } \
}while(0)

// ---- destructive 32-way merge of per-lane sorted lists; lane rr gets rank-rr key ----
#define MERGE15(KARR, MYVAL, LASTMN) do{ \
    unsigned long long head_ = KARR[0], mn_ = 0; \
    _Pragma("unroll") \
    for (int rr = 0; rr < EK; rr++){ \
        mn_ = head_; \
        _Pragma("unroll") \
        for (int o = 16; o > 0; o >>= 1) \
            mn_ = umin64(mn_, __shfl_xor_sync(0xffffffffu, mn_, o)); \
        if (head_ == mn_){ \
            _Pragma("unroll") \
            for (int s = 0; s < EK-1; s++) KARR[s] = KARR[s+1]; \
            KARR[EK-1] = ~0ULL; \
        } \
        head_ = KARR[0]; \
        if (lane == rr) (MYVAL) = mn_; \
    } \
    (LASTMN) = mn_; \
}while(0)

// ---------------- K4: exact 15-NN — warp per row, grid-pruned, full-scan fallback ----------------
// Warp-uniform 5x5x5 cell box (lanes parallelize over cell slots); per-lane u64 key lists
// (ord(d2), rank): unique keys -> order-free key-min == lax.top_k (ties -> lower idx).
// Stop proof: unvisited in-grid cells have Chebyshev >= 3 -> true d2 >= (2h)^2; computed
// d2 deviates <= ~3e-7, so merged d15 < (2h)^2 - 1e-6 certifies the top-15. Otherwise the
// warp redoes the row by exact full scan over all 4000 (R14-proven path). NaN d15 (list
// not full) fails the test -> fallback. Deterministic: path depends only on inputs.
__global__ void __launch_bounds__(256) k_knn_pos(){
    int lane = threadIdx.x & 31, wrp = threadIdx.x >> 5;
    int r = blockIdx.x*8 + wrp;                   // 500 blocks x 8 rows
    float4 m = *reinterpret_cast<const float4*>(&g_sp[r*4]);
    float px = m.x, py = m.y, pz = m.z, sqi = m.w;
    int cx = min(GC-1, max(0, (int)(px*GC)));
    int cy = min(GC-1, max(0, (int)(py*GC)));
    int cz = min(GC-1, max(0, (int)(pz*GC)));
    const float h = 1.0f/GC;
    unsigned long long k[EK];
    #pragma unroll
    for (int s = 0; s < EK; s++) k[s] = ~0ULL;
    // phase A: lanes cover the 125 cell slots of the radius-2 box
    for (int slot = lane; slot < 125; slot += 32){
        int dz = slot/25 - 2, dy = (slot/5)%5 - 2, dx = slot%5 - 2;
        int z = cz + dz, y = cy + dy, x = cx + dx;
        if ((unsigned)z >= GC || (unsigned)y >= GC || (unsigned)x >= GC) continue;
        int cell = (z*GC + y)*GC + x;
        int e1 = g_cellstart[cell+1];
        for (int e = g_cellstart[cell]; e < e1; e++){
            int sc = g_ci[e];
            if (sc >= NS || sc == r) continue;
            float4 q = g_cp[e];
            // acc=0; fma k=0,1,2 -> fma(z,qz, fma(y,qy, round(x*qx)))  [pass bits]
            float dot = __fmaf_rn(pz, q.z, __fmaf_rn(py, q.y, __fmul_rn(px, q.x)));
            float d2  = __fsub_rn(__fadd_rn(sqi, q.w), __fmul_rn(2.f, dot));
            unsigned long long key = ((unsigned long long)ord_f(d2) << 32) | (unsigned)sc;
            INSKEY(k, key);
        }
    }
    unsigned long long myval = ~0ULL, last = ~0ULL;
    MERGE15(k, myval, last);
    float d15 = iord_f((unsigned)(last >> 32));
    float bnd = __fmaf_rn(2.f*h, 2.f*h, -1e-6f);
    if (!(d15 < bnd)){                            // NaN or too large -> exact full scan
        #pragma unroll
        for (int s = 0; s < EK; s++) k[s] = ~0ULL;
        const int S = NS/32, lo = lane*S;         // disjoint 125-wide slices
        for (int u = 0; u < S; u++){
            int c = lo + u;
            float4 q = *reinterpret_cast<const float4*>(&g_sp[c*4]);
            float dot = __fmaf_rn(pz, q.z, __fmaf_rn(py, q.y, __fmul_rn(px, q.x)));
            float d2  = __fsub_rn(__fadd_rn(sqi, q.w), __fmul_rn(2.f, dot));
            if (c != r){
                unsigned long long key = ((unsigned long long)ord_f(d2) << 32) | (unsigned)c;
                INSKEY(k, key);
            }
        }
        MERGE15(k, myval, last);
    }
    if (lane < EK) g_nbr[r*EK + lane] = (int)(myval & 0xFFFFFFFFu);
}

// ---------------- K0: zero adjacency (after knn, before edges) ----------------
__global__ void __launch_bounds__(256) k_zero_adj(){
    float4 z = make_float4(0.f,0.f,0.f,0.f);
    float4* p = reinterpret_cast<float4*>(g_adj);
    const int n4 = (NS*NS)/4;
    for (int i = blockIdx.x*blockDim.x + threadIdx.x; i < n4; i += gridDim.x*blockDim.x)
        p[i] = z;
}

// ---------------- K5: edge probs, warp per edge (XLA mult+row-reduce shape) ----------------
__global__ void __launch_bounds__(256) k_edges(const float* __restrict__ we){
    int e = blockIdx.x*8 + (threadIdx.x >> 5);
    int lane = threadIdx.x & 31;
    if (e >= NS*EK) return;
    int i = e / EK;
    int j = g_nbr[e];
    const float* a = &g_sx[i*DD];
    const float* b = &g_sx[j*DD];
    // z_k = round(a_k*b_k); m_k = round(z_k*w_k); lane partial = m_lane + m_{lane+32}
    float m0 = __fmul_rn(__fmul_rn(a[lane],      b[lane]),      we[lane]);
    float m1 = __fmul_rn(__fmul_rn(a[lane + 32], b[lane + 32]), we[lane + 32]);
    float s  = __fadd_rn(m0, m1);
    s = warp_red_xla(s);
    if (lane == 0){
        float ep = sigmoid_xla(s);
        g_adj[i*NS + j] = ep;    // symmetric/duplicate writes identical bits: race-free
        g_adj[j*NS + i] = ep;
    }
}

// ---------------- K6: per-row sparse nz lists (column-ascending, deterministic) ----------------
__global__ void __launch_bounds__(256) k_nzlist(){
    int wid  = (blockIdx.x*blockDim.x + threadIdx.x) >> 5;
    int lane = threadIdx.x & 31;
    if (wid >= NS) return;
    int cnt = 0;
    for (int base = 0; base < NS; base += 32){
        float v = g_adj[wid*NS + base + lane];
        unsigned m = __ballot_sync(0xffffffffu, v != 0.f);
        if (v != 0.f){
            int pos = cnt + __popc(m & ((1u << lane) - 1u));
            if (pos < MAXDEG){ g_nzc[wid*MAXDEG + pos] = base + lane; g_nzv[wid*MAXDEG + pos] = v; }
        }
        cnt += __popc(m);
    }
    int deg = min(cnt, MAXDEG);
    if (lane == 0){
        g_deg[wid] = deg;
        // ||row||^2: ascending-column sequential (zeros contribute exact 0 in any order)
        float s = 0.f;
        for (int t = 0; t < deg; t++){
            float v = g_nzv[wid*MAXDEG + t];
            s = __fadd_rn(s, __fmul_rn(v, v));
        }
        g_sqadj[wid] = s;
    }
}

// ---------------- K7: sparse adj@adjT row, fd2, exact 16-NN (prefetch pipeline) ----------------
__global__ void __launch_bounds__(256) k_fd2knn(){
    __shared__ float sfd[NS];                    // 16 KB accumulate buffer
    __shared__ int   sic[MAXDEG];
    __shared__ float siv[MAXDEG];
    __shared__ int   sdeg[MAXDEG];
    __shared__ unsigned long long swin[8];
    __shared__ unsigned long long sbest;
    int i = blockIdx.x, t = threadIdx.x;         // 256 threads
    int lane = t & 31, warp = t >> 5;
    for (int k = t; k < NS; k += 256) sfd[k] = 0.f;
    int degi = g_deg[i];
    if (t < degi){ sic[t] = g_nzc[i*MAXDEG + t]; siv[t] = g_nzv[i*MAXDEG + t]; }
    __syncthreads();
    if (t < degi) sdeg[t] = g_deg[sic[t]];       // all neighbor degrees up front
    __syncthreads();
    // depth-2 software prefetch: (col,val) for iterations jj and jj+1 live in registers
    int   c0 = -1, c1 = -1;
    float v0 = 0.f, v1 = 0.f;
    if (0 < degi && t < sdeg[0]){ c0 = g_nzc[sic[0]*MAXDEG + t]; v0 = g_nzv[sic[0]*MAXDEG + t]; }
    if (1 < degi && t < sdeg[1]){ c1 = g_nzc[sic[1]*MAXDEG + t]; v1 = g_nzv[sic[1]*MAXDEG + t]; }
    for (int jj = 0; jj < degi; jj++){           // ascending-j == dense ascending-k bitwise
        int   c2 = -1; float v2 = 0.f;
        if (jj + 2 < degi && t < sdeg[jj+2]){    // issue next loads before the barrier
            c2 = g_nzc[sic[jj+2]*MAXDEG + t];
            v2 = g_nzv[sic[jj+2]*MAXDEG + t];
        }
        float aij = siv[jj];
        if (c0 >= 0) sfd[c0] = __fmaf_rn(aij, v0, sfd[c0]);  // distinct k within one j
        __syncthreads();
        c0 = c1; v0 = v1; c1 = c2; v1 = v2;
    }
    float sqi = g_sqadj[i];
    unsigned long long lk[16];
    #pragma unroll
    for (int m = 0; m < 16; m++){
        int k = t + 256*m;
        unsigned long long key = ~0ULL;
        if (k < NS && k != i){
            float fd = __fsub_rn(__fadd_rn(sqi, g_sqadj[k]), __fmul_rn(2.f, sfd[k]));
            key = ((unsigned long long)ord_f(fd) << 32) | (unsigned)k;
        }
        lk[m] = key;
    }
    unsigned long long lmin = lk[0];
    #pragma unroll
    for (int m = 1; m < 16; m++) lmin = umin64(lmin, lk[m]);
    for (int r = 0; r < KK; r++){
        unsigned long long b = lmin;
        #pragma unroll
        for (int o = 16; o > 0; o >>= 1) b = umin64(b, __shfl_down_sync(0xffffffffu, b, o));
        if (lane == 0) swin[warp] = b;
        __syncthreads();
        if (t == 0){
            unsigned long long bb = swin[0];
            #pragma unroll
            for (int w = 1; w < 8; w++) bb = umin64(bb, swin[w]);
            sbest = bb;
            g_knn[i*KK + r] = (int)(bb & 0xFFFFFFFFu);
        }
        __syncthreads();
        unsigned long long best = sbest;
        if (lmin == best){                       // unique key (idx embedded): one owner
            #pragma unroll
            for (int m = 0; m < 16; m++) if (lk[m] == best) lk[m] = ~0ULL;
            lmin = lk[0];
            #pragma unroll
            for (int m = 1; m < 16; m++) lmin = umin64(lmin, lk[m]);
        }
        __syncthreads();
    }
}

// ---------------- K8: triangles, warp per pair (XLA matvec reduce for hf@wf2) ----------------
__global__ void __launch_bounds__(256) k_tri(const float* __restrict__ bf1,
                      const float* __restrict__ wf2,
                      float* __restrict__ out){
    __shared__ int   sk[KK];
    __shared__ float sAi[KK];
    __shared__ float sGi[HH];
    __shared__ float sGn[KK][HH+4];              // padded to dodge bank conflicts
    __shared__ float sb[HH], sw[HH];
    int i = blockIdx.x, t = threadIdx.x;         // 256 threads, 8 warps
    int lane = t & 31, warp = t >> 5;
    if (t < KK) sk[t] = g_knn[i*KK + t];
    if (t < HH){ sGi[t] = g_G[i*HH + t]; sb[t] = bf1[t]; sw[t] = wf2[t]; }
    __syncthreads();
    if (t < KK) sAi[t] = g_adj[i*NS + sk[t]];
    for (int q = warp; q < KK; q += 8){
        sGn[q][lane]      = g_G[sk[q]*HH + lane];
        sGn[q][lane+32]   = g_G[sk[q]*HH + lane + 32];
        sGn[q][lane+64]   = g_G[sk[q]*HH + lane + 64];
        sGn[q][lane+96]   = g_G[sk[q]*HH + lane + 96];
    }
    __syncthreads();
    const float third = 1.0f/3.0f;
    #pragma unroll
    for (int it = 0; it < NPAIR/8; it++){        // 15 iterations x 8 warps = 120 pairs
        int p0 = it*8 + warp;
        int p = p0, j = 0;
        while (p >= (KK - 1 - j)){ p -= (KK - 1 - j); j++; }   // triu_indices(16,1) order
        int l = j + 1 + p;
        // hf@wf2: lane partials k=lane+32m (rounded products, sequential adds), butterfly
        float s = 0.f;
        #pragma unroll
        for (int m = 0; m < 4; m++){
            int k = lane + 32*m;
            float pre = (sGi[k] + sGn[j][k] + sGn[l][k]) * third + sb[k];  // value-only path
            float hf  = fmaxf(pre, 0.f);
            s = __fadd_rn(s, __fmul_rn(hf, sw[k]));
        }
        s = warp_red_xla(s);
        if (lane == 0){
            int n1 = sk[j], n2 = sk[l];
            float a12  = g_adj[n1*NS + n2];
            bool valid = a12 > 0.f;
            float prod = __fmul_rn(__fmul_rn(sAi[j], sAi[l]), a12);
            float tpr  = valid ? cbrtf(fmaxf(prod, 1e-9f)) : 0.f;
            float fpr  = valid ? sigmoid_xla(s) : 0.f;
            out[i*NPAIR + p0]        = fpr;
            out[OUTM + i*NPAIR + p0] = tpr;
        }
    }
}

// ---------------- launch ----------------
extern "C" void kernel_launch(void* const* d_in, const int* in_sizes, int n_in,
                              void* d_out, int out_size){
    (void)in_sizes; (void)n_in; (void)out_size;
    const float* x   = (const float*)d_in[0];
    const float* pos = (const float*)d_in[1];
    const float* W1  = (const float*)d_in[2];
    const float* b1  = (const float*)d_in[3];
    const float* w2  = (const float*)d_in[4];
    const float* we  = (const float*)d_in[5];
    const float* Wf1 = (const float*)d_in[6];
    const float* bf1 = (const float*)d_in[7];
    const float* wf2 = (const float*)d_in[8];
    float* out = (float*)d_out;

    k_probs<<<NN/4, 128>>>(x, W1, b1, w2);       // idx 0
    k_grid_zero<<<1, 256>>>();                   // idx 1
    k_grid_bin<<<(NN+255)/256, 256>>>(pos);      // idx 2
    k_rank_a<<<128, 256>>>();                    // idx 3  <- ncu capture target
    k_grid_scan<<<1, 256>>>();                   // idx 4
    k_grid_scatter<<<(NN+255)/256, 256>>>(pos);  // idx 5 (needs g_cnt + scan)
    k_sel_gather<<<NN/8, 256>>>(x, pos, Wf1);    // idx 6
    k_knn_pos<<<500, 256>>>();                   // idx 7 (warp-per-row grid kNN)
    k_zero_adj<<<1184, 256>>>();                 // idx 8
    k_edges<<<(NS*EK + 7)/8, 256>>>(we);         // idx 9
    k_nzlist<<<NS/8, 256>>>();                   // idx 10
    k_fd2knn<<<NS, 256>>>();                     // idx 11
    k_tri<<<NS, 256>>>(bf1, wf2, out);           // idx 12
}

// round 17
// speedup vs baseline: 1.6949x; 1.0500x over previous
#include <cuda_runtime.h>
#include <math.h>
#include <stdint.h>

#define NN 8000
#define NS 4000
#define DD 64
#define HH 128
#define EK 15
#define KK 16
#define MAXDEG 256
#define NPAIR 120
#define OUTM (NS*NPAIR)
#define GC 16
#define NCELL (GC*GC*GC)

// ---------------- device scratch (static, no dynamic allocation) ----------------
__device__ __align__(16) float g_adj[NS*NS];          // 64 MB dense symmetric adjacency
__device__ unsigned long long g_key[NN];
__device__ int   g_cnt[NN];
__device__ __align__(16) float g_sx[NS*DD];
__device__ __align__(16) float g_sp[NS*4];            // x,y,z,sq
__device__ float g_G[NS*HH];
__device__ int   g_nbr[NS*EK];
__device__ int   g_deg[NS];
__device__ __align__(16) int   g_nzc[NS*MAXDEG];
__device__ __align__(16) float g_nzv[NS*MAXDEG];
__device__ float g_sqadj[NS];
__device__ int   g_knn[NS*KK];
// grid structures for exact kNN pruning
__device__ int   g_ccount[NCELL];
__device__ int   g_cellstart[NCELL+1];
__device__ int   g_ccur[NCELL];
__device__ int   g_cellof[NN];
__device__ __align__(16) float4 g_cp[NN];             // cell-sorted (pos, sq)
__device__ int   g_ci[NN];                            // cell-sorted selected-rank (>=NS if unselected)

__device__ __forceinline__ unsigned ord_f(float f){
    unsigned u = __float_as_uint(f);
    return (u & 0x80000000u) ? ~u : (u | 0x80000000u);   // ascending-float -> ascending-uint
}
__device__ __forceinline__ float iord_f(unsigned o){
    unsigned u = (o & 0x80000000u) ? (o & 0x7fffffffu) : ~o;
    return __uint_as_float(u);
}
__device__ __forceinline__ unsigned long long umin64(unsigned long long a, unsigned long long b){
    return a < b ? a : b;
}

// ---- XLA/Eigen fast tanh (f32), bit-exact replication ----
__device__ __forceinline__ float tanh_xla(float x){
    float ax = fabsf(x);
    if (ax < 0.0004f) return x;                           // XLA kCanUseApprox shortcut
    float xc = fminf(fmaxf(x, -7.90531110763549805f), 7.90531110763549805f);
    float x2 = __fmul_rn(xc, xc);
    float p = __fmaf_rn(x2, -2.76076847742355e-16f, 2.00018790482477e-13f);
    p = __fmaf_rn(x2, p, -8.60467152213735e-11f);
    p = __fmaf_rn(x2, p,  5.12229709037114e-08f);
    p = __fmaf_rn(x2, p,  1.48572235717979e-05f);
    p = __fmaf_rn(x2, p,  6.37261928875436e-04f);
    p = __fmaf_rn(x2, p,  4.89352455891786e-03f);
    p = __fmul_rn(p, xc);
    float q = __fmaf_rn(x2, 1.19825839466702e-06f, 1.18534705686654e-04f);
    q = __fmaf_rn(x2, q, 2.26843463243900e-03f);
    q = __fmaf_rn(x2, q, 4.89352518554385e-03f);
    return __fdiv_rn(p, q);
}
// XLA logistic expansion: 0.5 + 0.5 * tanh(0.5 * x)
__device__ __forceinline__ float sigmoid_xla(float v){
    return __fadd_rn(0.5f, __fmul_rn(0.5f, tanh_xla(__fmul_rn(0.5f, v))));
}
// XLA row-reduction warp tail: shfl_down butterfly 16..1, result in lane 0
__device__ __forceinline__ float warp_red_xla(float s){
    #pragma unroll
    for (int o = 16; o > 0; o >>= 1)
        s = __fadd_rn(s, __shfl_down_sync(0xffffffffu, s, o));
    return s;
}

// ---------------- K1: probs + grid-counter zeroing (fused) ----------------
__global__ void __launch_bounds__(128) k_probs(const float* __restrict__ x,
                        const float* __restrict__ W1,
                        const float* __restrict__ b1, const float* __restrict__ w2){
    __shared__ float xs[4][DD];
    __shared__ float sW1[DD*HH];                // 32 KB
    int warp = threadIdx.x >> 5, lane = threadIdx.x & 31;
    // fold: zero grid counters (complete before k_rank_a's bin atomics — kernel boundary)
    int gz = blockIdx.x*128 + threadIdx.x;
    if (gz < NCELL) g_ccount[gz] = 0;
    const float4* wsrc = reinterpret_cast<const float4*>(W1);
    float4* wdst = reinterpret_cast<float4*>(sW1);
    #pragma unroll
    for (int u = 0; u < (DD*HH/4)/128; u++)
        wdst[threadIdx.x + 128*u] = wsrc[threadIdx.x + 128*u];
    int n = blockIdx.x*4 + warp;                // 8000 nodes, 4 warps/block, grid=2000
    if (lane == 0) g_cnt[n] = 0;                // reset rank counter for this replay
    xs[warp][lane]      = x[n*DD + lane];
    xs[warp][lane + 32] = x[n*DD + lane + 32];
    __syncthreads();
    float s = 0.f;
    #pragma unroll
    for (int j = 0; j < 4; j++){
        int k = lane + 32*j;
        float h = 0.f;
        #pragma unroll
        for (int d = 0; d < DD; d++) h = __fmaf_rn(xs[warp][d], sW1[d*HH + k], h);
        h = fmaxf(__fadd_rn(h, b1[k]), 0.f);
        float m = __fmul_rn(h, w2[k]);
        s = __fadd_rn(s, m);                    // sequential ascending-j adds
    }
    s = warp_red_xla(s);
    if (lane == 0){
        float p = sigmoid_xla(s);
        g_key[n] = ((unsigned long long)ord_f(p) << 32) | (unsigned)(NN - 1 - n); // tie->lower n
    }
}

// ---------------- K2a: partial exact ranking + grid binning (fused) ----------------
__global__ void __launch_bounds__(256) k_rank_a(const float* __restrict__ pos){
    __shared__ unsigned long long sk[256];
    // fold: bin nodes into cells (counters zeroed by k_probs; scan reads after boundary)
    if (blockIdx.x < 32){
        int n2 = blockIdx.x*256 + threadIdx.x;
        if (n2 < NN){
            float px = pos[n2*3], py = pos[n2*3+1], pz = pos[n2*3+2];
            int cx = min(GC-1, max(0, (int)(px*GC)));
            int cy = min(GC-1, max(0, (int)(py*GC)));
            int cz = min(GC-1, max(0, (int)(pz*GC)));
            int cell = (cz*GC + cy)*GC + cx;
            g_cellof[n2] = cell;
            atomicAdd(&g_ccount[cell], 1);
        }
    }
    int qt = blockIdx.x >> 5;                   // quarter 0..3
    int nb = blockIdx.x & 31;                   // node block 0..31
    int n = nb*256 + threadIdx.x;               // 0..8191
    unsigned long long my = (n < NN) ? g_key[n] : 0ULL;
    int cnt = 0;
    int lo = qt*(NN/4), hi = lo + NN/4;         // 2000-wide key range
    for (int base = lo; base < hi; base += 256){
        int idx = base + threadIdx.x;
        sk[threadIdx.x] = (idx < hi) ? g_key[idx] : 0ULL;
        __syncthreads();
        int lim = min(256, hi - base);
        for (int k = 0; k < lim; k++) cnt += (sk[k] > my) ? 1 : 0;
        __syncthreads();
    }
    if (n < NN && cnt > 0) atomicAdd(&g_cnt[n], cnt);   // int add: order-independent exact
}

// ---------------- G2: exclusive prefix sum over 4096 cells (single block) ----------------
__global__ void __launch_bounds__(256) k_grid_scan(){
    __shared__ int part[256];
    int tid = threadIdx.x;
    int base = tid*(NCELL/256);
    int s = 0;
    #pragma unroll
    for (int i = 0; i < NCELL/256; i++) s += g_ccount[base+i];
    part[tid] = s;
    __syncthreads();
    if (tid == 0){
        int acc = 0;
        for (int i = 0; i < 256; i++){ int t = part[i]; part[i] = acc; acc += t; }
    }
    __syncthreads();
    int acc = part[tid];
    #pragma unroll
    for (int i = 0; i < NCELL/256; i++){
        int t = g_ccount[base+i];
        g_cellstart[base+i] = acc;
        g_ccur[base+i] = acc;
        acc += t;
    }
    if (tid == 255) g_cellstart[NCELL] = NN;
}

// ---------------- K2b+K3 fused (+ grid scatter): each selected node writes its own row ----------------
__global__ void __launch_bounds__(256) k_sel_gather(const float* __restrict__ x,
                         const float* __restrict__ pos,
                         const float* __restrict__ Wf1){
    __shared__ float xs[8][DD];
    // fold: scatter nodes into cell order (needs g_cnt + g_cellstart/g_ccur; knn reads after
    // the next kernel boundary). sq uses the SAME op sequence as below -> bit-identical.
    {
        int n2 = blockIdx.x*256 + threadIdx.x;   // blocks 0..31 cover all 8000 nodes
        if (n2 < NN){
            float px = pos[n2*3], py = pos[n2*3+1], pz = pos[n2*3+2];
            float sq = __fadd_rn(__fadd_rn(__fmul_rn(px,px), __fmul_rn(py,py)), __fmul_rn(pz,pz));
            int off = atomicAdd(&g_ccur[g_cellof[n2]], 1);   // within-cell order nondet: OK,
            g_cp[off] = make_float4(px, py, pz, sq);         // selection is key-min (order-free)
            g_ci[off] = g_cnt[n2];                           // rank; >=NS if unselected
        }
    }
    int warp = threadIdx.x >> 5, lane = threadIdx.x & 31;
    int n = blockIdx.x*8 + warp;                // 1000 blocks x 8 warps = 8000 nodes
    int c = g_cnt[n];
    if (c >= NS) return;                        // not selected: whole warp exits
    int r = c;
    float x0 = x[n*DD + lane], x1 = x[n*DD + lane + 32];
    xs[warp][lane] = x0; xs[warp][lane + 32] = x1;
    g_sx[r*DD + lane] = x0; g_sx[r*DD + lane + 32] = x1;
    float pv = (lane < 3) ? pos[n*3 + lane] : 0.f;
    if (lane < 3) g_sp[r*4 + lane] = pv;
    float ppx = __shfl_sync(0xffffffffu, pv, 0);
    float ppy = __shfl_sync(0xffffffffu, pv, 1);
    float ppz = __shfl_sync(0xffffffffu, pv, 2);
    if (lane == 0){
        // sq = (x^2 + y^2) + z^2, squares rounded separately (square-then-reduce, NO fma)
        float sq = __fadd_rn(__fadd_rn(__fmul_rn(ppx,ppx), __fmul_rn(ppy,ppy)),
                             __fmul_rn(ppz,ppz));
        g_sp[r*4 + 3] = sq;
    }
    __syncwarp();
    float g0 = 0.f, g1 = 0.f, g2 = 0.f, g3 = 0.f;
    int t0 = lane, t1 = lane + 32, t2 = lane + 64, t3 = lane + 96;
    #pragma unroll
    for (int d = 0; d < DD; d++){
        float v = xs[warp][d];
        const float* wrow = &Wf1[d*HH];
        g0 = fmaf(v, wrow[t0], g0);
        g1 = fmaf(v, wrow[t1], g1);
        g2 = fmaf(v, wrow[t2], g2);
        g3 = fmaf(v, wrow[t3], g3);
    }
    {
        const float* wrow = &Wf1[DD*HH];
        g0 = fmaf(ppx, wrow[t0], g0); g1 = fmaf(ppx, wrow[t1], g1);
        g2 = fmaf(ppx, wrow[t2], g2); g3 = fmaf(ppx, wrow[t3], g3);
        wrow += HH;
        g0 = fmaf(ppy, wrow[t0], g0); g1 = fmaf(ppy, wrow[t1], g1);
        g2 = fmaf(ppy, wrow[t2], g2); g3 = fmaf(ppy, wrow[t3], g3);
        wrow += HH;
        g0 = fmaf(ppz, wrow[t0], g0); g1 = fmaf(ppz, wrow[t1], g1);
        g2 = fmaf(ppz, wrow[t2], g2); g3 = fmaf(ppz, wrow[t3], g3);
    }
    g_G[r*HH + t0] = g0; g_G[r*HH + t1] = g1;
    g_G[r*HH + t2] = g2; g_G[r*HH + t3] = g3;
}

// ---- guarded exact insertion into a sorted 15-key register list ----
#define INSKEY(KARR, KEY) do{ \
    if ((KEY) < KARR[EK-1]){ \
        int pos = 0; \
        _Pragma("unroll") \
        for (int s = 0; s < EK; s++) pos += (KARR[s] <= (KEY)) ? 1 : 0; \
        _Pragma("unroll") \
        for (int s = EK-1; s > 0; s--) if (s > pos) KARR[s] = KARR[s-1]; \
        _Pragma("unroll") \
        for (int s = 0; s < EK; s++) if (s == pos) KARR[s] = (KEY); \
    } \
}while(0)

// ---- destructive 32-way merge of per-lane sorted lists; lane rr gets rank-rr key ----
#define MERGE15(KARR, MYVAL, LASTMN) do{ \
    unsigned long long head_ = KARR[0], mn_ = 0; \
    _Pragma("unroll") \
    for (int rr = 0; rr < EK; rr++){ \
        mn_ = head_; \
        _Pragma("unroll") \
        for (int o = 16; o > 0; o >>= 1) \
            mn_ = umin64(mn_, __shfl_xor_sync(0xffffffffu, mn_, o)); \
        if (head_ == mn_){ \
            _Pragma("unroll") \
            for (int s = 0; s < EK-1; s++) KARR[s] = KARR[s+1]; \
            KARR[EK-1] = ~0ULL; \
        } \
        head_ = KARR[0]; \
        if (lane == rr) (MYVAL) = mn_; \
    } \
    (LASTMN) = mn_; \
}while(0)

// ---------------- K4: exact 15-NN (grid-pruned, fallback) + adjacency zeroing (fused) ----------------
__global__ void __launch_bounds__(256) k_knn_pos(){
    int lane = threadIdx.x & 31, wrp = threadIdx.x >> 5;
    int r = blockIdx.x*8 + wrp;                   // 500 blocks x 8 rows
    float4 m = *reinterpret_cast<const float4*>(&g_sp[r*4]);
    float px = m.x, py = m.y, pz = m.z, sqi = m.w;
    int cx = min(GC-1, max(0, (int)(px*GC)));
    int cy = min(GC-1, max(0, (int)(py*GC)));
    int cz = min(GC-1, max(0, (int)(pz*GC)));
    const float h = 1.0f/GC;
    unsigned long long k[EK];
    #pragma unroll
    for (int s = 0; s < EK; s++) k[s] = ~0ULL;
    // phase A: lanes cover the 125 cell slots of the radius-2 box (warp-uniform)
    for (int slot = lane; slot < 125; slot += 32){
        int dz = slot/25 - 2, dy = (slot/5)%5 - 2, dx = slot%5 - 2;
        int z = cz + dz, y = cy + dy, x = cx + dx;
        if ((unsigned)z >= GC || (unsigned)y >= GC || (unsigned)x >= GC) continue;
        int cell = (z*GC + y)*GC + x;
        int e1 = g_cellstart[cell+1];
        for (int e = g_cellstart[cell]; e < e1; e++){
            int sc = g_ci[e];
            if (sc >= NS || sc == r) continue;
            float4 q = g_cp[e];
            // acc=0; fma k=0,1,2 -> fma(z,qz, fma(y,qy, round(x*qx)))  [pass bits]
            float dot = __fmaf_rn(pz, q.z, __fmaf_rn(py, q.y, __fmul_rn(px, q.x)));
            float d2  = __fsub_rn(__fadd_rn(sqi, q.w), __fmul_rn(2.f, dot));
            unsigned long long key = ((unsigned long long)ord_f(d2) << 32) | (unsigned)sc;
            INSKEY(k, key);
        }
    }
    unsigned long long myval = ~0ULL, last = ~0ULL;
    MERGE15(k, myval, last);
    float d15 = iord_f((unsigned)(last >> 32));
    float bnd = __fmaf_rn(2.f*h, 2.f*h, -1e-6f);
    if (!(d15 < bnd)){                            // NaN or too large -> exact full scan
        #pragma unroll
        for (int s = 0; s < EK; s++) k[s] = ~0ULL;
        const int S = NS/32, lo = lane*S;         // disjoint 125-wide slices
        for (int u = 0; u < S; u++){
            int c = lo + u;
            float4 q = *reinterpret_cast<const float4*>(&g_sp[c*4]);
            float dot = __fmaf_rn(pz, q.z, __fmaf_rn(py, q.y, __fmul_rn(px, q.x)));
            float d2  = __fsub_rn(__fadd_rn(sqi, q.w), __fmul_rn(2.f, dot));
            if (c != r){
                unsigned long long key = ((unsigned long long)ord_f(d2) << 32) | (unsigned)c;
                INSKEY(k, key);
            }
        }
        MERGE15(k, myval, last);
    }
    if (lane < EK) g_nbr[r*EK + lane] = (int)(myval & 0xFFFFFFFFu);
    // fold: zero dense adjacency (completes before k_edges' writes — kernel boundary)
    {
        float4 z4 = make_float4(0.f,0.f,0.f,0.f);
        float4* p = reinterpret_cast<float4*>(g_adj);
        const int n4 = (NS*NS)/4;
        int tg = blockIdx.x*256 + threadIdx.x;    // 128000 threads
        for (int i = tg; i < n4; i += 128000) p[i] = z4;
    }
}

// ---------------- K5: edge probs, warp per edge (XLA mult+row-reduce shape) ----------------
__global__ void __launch_bounds__(256) k_edges(const float* __restrict__ we){
    int e = blockIdx.x*8 + (threadIdx.x >> 5);
    int lane = threadIdx.x & 31;
    if (e >= NS*EK) return;
    int i = e / EK;
    int j = g_nbr[e];
    const float* a = &g_sx[i*DD];
    const float* b = &g_sx[j*DD];
    // z_k = round(a_k*b_k); m_k = round(z_k*w_k); lane partial = m_lane + m_{lane+32}
    float m0 = __fmul_rn(__fmul_rn(a[lane],      b[lane]),      we[lane]);
    float m1 = __fmul_rn(__fmul_rn(a[lane + 32], b[lane + 32]), we[lane + 32]);
    float s  = __fadd_rn(m0, m1);
    s = warp_red_xla(s);
    if (lane == 0){
        float ep = sigmoid_xla(s);
        g_adj[i*NS + j] = ep;    // symmetric/duplicate writes identical bits: race-free
        g_adj[j*NS + i] = ep;
    }
}

// ---------------- K6: per-row sparse nz lists (column-ascending, deterministic) ----------------
__global__ void __launch_bounds__(256) k_nzlist(){
    int wid  = (blockIdx.x*blockDim.x + threadIdx.x) >> 5;
    int lane = threadIdx.x & 31;
    if (wid >= NS) return;
    int cnt = 0;
    for (int base = 0; base < NS; base += 32){
        float v = g_adj[wid*NS + base + lane];
        unsigned m = __ballot_sync(0xffffffffu, v != 0.f);
        if (v != 0.f){
            int pos = cnt + __popc(m & ((1u << lane) - 1u));
            if (pos < MAXDEG){ g_nzc[wid*MAXDEG + pos] = base + lane; g_nzv[wid*MAXDEG + pos] = v; }
        }
        cnt += __popc(m);
    }
    int deg = min(cnt, MAXDEG);
    if (lane == 0){
        g_deg[wid] = deg;
        // ||row||^2: ascending-column sequential (zeros contribute exact 0 in any order)
        float s = 0.f;
        for (int t = 0; t < deg; t++){
            float v = g_nzv[wid*MAXDEG + t];
            s = __fadd_rn(s, __fmul_rn(v, v));
        }
        g_sqadj[wid] = s;
    }
}

// ---------------- K7: sparse adj@adjT row, fd2, exact 16-NN (depth-3 prefetch) ----------------
__global__ void __launch_bounds__(256) k_fd2knn(){
    __shared__ float sfd[NS];                    // 16 KB accumulate buffer
    __shared__ int   sic[MAXDEG];
    __shared__ float siv[MAXDEG];
    __shared__ int   sdeg[MAXDEG];
    __shared__ unsigned long long swin[8];
    __shared__ unsigned long long sbest;
    int i = blockIdx.x, t = threadIdx.x;         // 256 threads
    int lane = t & 31, warp = t >> 5;
    for (int k = t; k < NS; k += 256) sfd[k] = 0.f;
    int degi = g_deg[i];
    if (t < degi){ sic[t] = g_nzc[i*MAXDEG + t]; siv[t] = g_nzv[i*MAXDEG + t]; }
    __syncthreads();
    if (t < degi) sdeg[t] = g_deg[sic[t]];       // all neighbor degrees up front
    __syncthreads();
    // depth-3 software prefetch: covers L2 latency (~234-577 cy) across ~3 iteration bodies
    int   c0 = -1, c1 = -1, c2 = -1;
    float v0 = 0.f, v1 = 0.f, v2 = 0.f;
    if (0 < degi && t < sdeg[0]){ c0 = g_nzc[sic[0]*MAXDEG + t]; v0 = g_nzv[sic[0]*MAXDEG + t]; }
    if (1 < degi && t < sdeg[1]){ c1 = g_nzc[sic[1]*MAXDEG + t]; v1 = g_nzv[sic[1]*MAXDEG + t]; }
    if (2 < degi && t < sdeg[2]){ c2 = g_nzc[sic[2]*MAXDEG + t]; v2 = g_nzv[sic[2]*MAXDEG + t]; }
    for (int jj = 0; jj < degi; jj++){           // ascending-j == dense ascending-k bitwise
        int   c3 = -1; float v3 = 0.f;
        if (jj + 3 < degi && t < sdeg[jj+3]){    // issue next loads before the barrier
            c3 = g_nzc[sic[jj+3]*MAXDEG + t];
            v3 = g_nzv[sic[jj+3]*MAXDEG + t];
        }
        float aij = siv[jj];
        if (c0 >= 0) sfd[c0] = __fmaf_rn(aij, v0, sfd[c0]);  // distinct k within one j
        __syncthreads();
        c0 = c1; v0 = v1; c1 = c2; v1 = v2; c2 = c3; v2 = v3;
    }
    float sqi = g_sqadj[i];
    unsigned long long lk[16];
    #pragma unroll
    for (int m = 0; m < 16; m++){
        int k = t + 256*m;
        unsigned long long key = ~0ULL;
        if (k < NS && k != i){
            float fd = __fsub_rn(__fadd_rn(sqi, g_sqadj[k]), __fmul_rn(2.f, sfd[k]));
            key = ((unsigned long long)ord_f(fd) << 32) | (unsigned)k;
        }
        lk[m] = key;
    }
    unsigned long long lmin = lk[0];
    #pragma unroll
    for (int m = 1; m < 16; m++) lmin = umin64(lmin, lk[m]);
    for (int r = 0; r < KK; r++){
        unsigned long long b = lmin;
        #pragma unroll
        for (int o = 16; o > 0; o >>= 1) b = umin64(b, __shfl_down_sync(0xffffffffu, b, o));
        if (lane == 0) swin[warp] = b;
        __syncthreads();
        if (t == 0){
            unsigned long long bb = swin[0];
            #pragma unroll
            for (int w = 1; w < 8; w++) bb = umin64(bb, swin[w]);
            sbest = bb;
            g_knn[i*KK + r] = (int)(bb & 0xFFFFFFFFu);
        }
        __syncthreads();
        unsigned long long best = sbest;
        if (lmin == best){                       // unique key (idx embedded): one owner
            #pragma unroll
            for (int m = 0; m < 16; m++) if (lk[m] == best) lk[m] = ~0ULL;
            lmin = lk[0];
            #pragma unroll
            for (int m = 1; m < 16; m++) lmin = umin64(lmin, lk[m]);
        }
        __syncthreads();
    }
}

// ---------------- K8: triangles, warp per pair; a12 lane-prefetched (parallel L2) ----------------
__global__ void __launch_bounds__(256) k_tri(const float* __restrict__ bf1,
                      const float* __restrict__ wf2,
                      float* __restrict__ out){
    __shared__ int   sk[KK];
    __shared__ float sAi[KK];
    __shared__ float sGi[HH];
    __shared__ float sGn[KK][HH+4];              // padded to dodge bank conflicts
    __shared__ float sb[HH], sw[HH];
    int i = blockIdx.x, t = threadIdx.x;         // 256 threads, 8 warps
    int lane = t & 31, warp = t >> 5;
    if (t < KK) sk[t] = g_knn[i*KK + t];
    if (t < HH){ sGi[t] = g_G[i*HH + t]; sb[t] = bf1[t]; sw[t] = wf2[t]; }
    __syncthreads();
    if (t < KK) sAi[t] = g_adj[i*NS + sk[t]];
    for (int q = warp; q < KK; q += 8){
        sGn[q][lane]      = g_G[sk[q]*HH + lane];
        sGn[q][lane+32]   = g_G[sk[q]*HH + lane + 32];
        sGn[q][lane+64]   = g_G[sk[q]*HH + lane + 64];
        sGn[q][lane+96]   = g_G[sk[q]*HH + lane + 96];
    }
    __syncthreads();
    // prefetch this warp's 15 a12 values in parallel: lane it handles iteration it
    float a12pf = 0.f;
    if (lane < NPAIR/8){
        int p0 = lane*8 + warp;
        int p = p0, j = 0;
        while (p >= (KK - 1 - j)){ p -= (KK - 1 - j); j++; }
        int l = j + 1 + p;
        a12pf = g_adj[sk[j]*NS + sk[l]];
    }
    const float third = 1.0f/3.0f;
    #pragma unroll
    for (int it = 0; it < NPAIR/8; it++){        // 15 iterations x 8 warps = 120 pairs
        int p0 = it*8 + warp;
        int p = p0, j = 0;
        while (p >= (KK - 1 - j)){ p -= (KK - 1 - j); j++; }   // triu_indices(16,1) order
        int l = j + 1 + p;
        // hf@wf2: lane partials k=lane+32m (rounded products, sequential adds), butterfly
        float s = 0.f;
        #pragma unroll
        for (int m = 0; m < 4; m++){
            int k = lane + 32*m;
            float pre = (sGi[k] + sGn[j][k] + sGn[l][k]) * third + sb[k];  // value-only path
            float hf  = fmaxf(pre, 0.f);
            s = __fadd_rn(s, __fmul_rn(hf, sw[k]));
        }
        s = warp_red_xla(s);
        float a12 = __shfl_sync(0xffffffffu, a12pf, it);       // identical loaded bits
        if (lane == 0){
            bool valid = a12 > 0.f;
            float prod = __fmul_rn(__fmul_rn(sAi[j], sAi[l]), a12);
            float tpr  = valid ? cbrtf(fmaxf(prod, 1e-9f)) : 0.f;
            float fpr  = valid ? sigmoid_xla(s) : 0.f;
            out[i*NPAIR + p0]        = fpr;
            out[OUTM + i*NPAIR + p0] = tpr;
        }
    }
}

// ---------------- launch ----------------
extern "C" void kernel_launch(void* const* d_in, const int* in_sizes, int n_in,
                              void* d_out, int out_size){
    (void)in_sizes; (void)n_in; (void)out_size;
    const float* x   = (const float*)d_in[0];
    const float* pos = (const float*)d_in[1];
    const float* W1  = (const float*)d_in[2];
    const float* b1  = (const float*)d_in[3];
    const float* w2  = (const float*)d_in[4];
    const float* we  = (const float*)d_in[5];
    const float* Wf1 = (const float*)d_in[6];
    const float* bf1 = (const float*)d_in[7];
    const float* wf2 = (const float*)d_in[8];
    float* out = (float*)d_out;

    k_probs<<<NN/4, 128>>>(x, W1, b1, w2);       // idx 0 (+grid zero)
    k_rank_a<<<128, 256>>>(pos);                 // idx 1 (+grid bin)
    k_grid_scan<<<1, 256>>>();                   // idx 2
    k_sel_gather<<<NN/8, 256>>>(x, pos, Wf1);    // idx 3  <- ncu capture target (+scatter)
    k_knn_pos<<<500, 256>>>();                   // idx 4 (+adjacency zero)
    k_edges<<<(NS*EK + 7)/8, 256>>>(we);         // idx 5
    k_nzlist<<<NS/8, 256>>>();                   // idx 6
    k_fd2knn<<<NS, 256>>>();                     // idx 7
    k_tri<<<NS, 256>>>(bf1, wf2, out);           // idx 8
}